// round 6
// baseline (speedup 1.0000x reference)
#include <cuda_runtime.h>
#include <cuda_fp16.h>
#include <mma.h>
#include <math.h>
#include <cstdint>
#include <type_traits>
using namespace nvcuda;

#define BSZ 4
#define CDIM 512
#define NN 4096
#define MM 4096
#define DAD 128

#define BM 128
#define BN 128
#define BK 32
// padded smem leading dims (halves)
#define LD_K  40    // rows of BK(+8)   : [*][k]
#define LD_MN 136   // rows of 128(+8)  : [*][m or n]

// ---------------- scratch (device globals; no allocation) ----------------
__device__ __half g_xh[BSZ * CDIM * NN];
__device__ __half g_yh[BSZ * CDIM * MM];
__device__ __half g_wqk[DAD * CDIM];
__device__ __half g_wv[CDIM * CDIM];
__device__ __half g_wt[CDIM * CDIM];
__device__ __half g_q[BSZ * DAD * NN];           // [B,128,4096]
__device__ __half g_kx[BSZ * DAD * MM];          // [B,128,4096]
__device__ __half g_v[BSZ * CDIM * MM];          // [B,512,4096]
__device__ __half g_p[(size_t)BSZ * NN * MM];    // unnormalized exp(energy), half
__device__ __half g_o[BSZ * NN * CDIM];          // [B,4096,512]
__device__ float  g_inv[CDIM];
__device__ float  g_cadd[CDIM];

// ---------------- helpers ----------------
__device__ __forceinline__ void cp_async16(void* smem, const void* gmem) {
    unsigned s = (unsigned)__cvta_generic_to_shared(smem);
    asm volatile("cp.async.cg.shared.global [%0], [%1], 16;\n" :: "r"(s), "l"(gmem));
}
__device__ __forceinline__ void cp_commit() {
    asm volatile("cp.async.commit_group;\n");
}
__device__ __forceinline__ void cp_wait_all() {
    asm volatile("cp.async.wait_group 0;\n");
}

// ---------------- fp32 -> fp16 convert ----------------
__global__ void f2h_k(const float* __restrict__ in, __half* __restrict__ out, int n4) {
    int i = blockIdx.x * blockDim.x + threadIdx.x;
    if (i < n4) {
        float4 v = ((const float4*)in)[i];
        __half h[4] = { __float2half_rn(v.x), __float2half_rn(v.y),
                        __float2half_rn(v.z), __float2half_rn(v.w) };
        ((uint2*)out)[i] = *(uint2*)h;
    }
}

// ---------------- BN-fold precompute ----------------
__global__ void precomp_k(const float* __restrict__ gamma,
                          const float* __restrict__ beta,
                          const float* __restrict__ rmean,
                          const float* __restrict__ rvar,
                          const float* __restrict__ b_t) {
    int c = threadIdx.x;
    if (c < CDIM) {
        float inv = gamma[c] * rsqrtf(rvar[c] + 1e-5f);
        g_inv[c]  = inv;
        g_cadd[c] = b_t[c] * inv + beta[c] - rmean[c] * inv;
    }
}

// ---------------- pipelined tensor-core GEMM (half in, fp32 accum) ----------------
// C[m,n] = epi( sum_k A[m,k]*B[k,n] )
// TA=1: A stored [K,M] (lda=Mdim) -> smem As[k][m], col_major frag
// TA=0: A stored [M,K] (lda=Kdim) -> smem As[m][k], row_major frag
// TB=1: B stored [N,K] (ldb=Kdim) -> smem Bs[n][k], col_major frag
// TB=0: B stored [K,N] (ldb=Ndim) -> smem Bs[k][n], row_major frag
// EPI: 0 plain ; 1 +biasRow[m] ; 2 *alpha ; 4 relu(v*scaleCol[n]+addCol[n])
//      8 exp(alpha*v) ; 16 divide-by-rowsum-of-A (requires TA=0; softmax-normalize)
template <int TA, int TB, int EPI, typename CT>
__global__ __launch_bounds__(256, 2)
void hgemm_k(const __half* __restrict__ Ag, const __half* __restrict__ Bg,
             CT* __restrict__ Cg,
             int Mdim, int Ndim, int Kdim,
             long long sA, long long sB, long long sC,
             float alpha,
             const float* __restrict__ biasRow,
             const float* __restrict__ scaleCol,
             const float* __restrict__ addCol) {
    constexpr int A_HALVES = TA ? BK * LD_MN : BM * LD_K;   // per stage
    constexpr int B_HALVES = TB ? BN * LD_K  : BK * LD_MN;
    constexpr int STAGE = A_HALVES + B_HALVES;
    __shared__ __align__(16) __half smem[2 * STAGE];
    __shared__ float rowsumS[BM];
    float* Es = (float*)smem;   // epilogue reuse

    const __half* A = Ag + (long long)blockIdx.z * sA;
    const __half* B = Bg + (long long)blockIdx.z * sB;
    CT*           C = Cg + (long long)blockIdx.z * sC;

    const int row0 = blockIdx.y * BM;
    const int col0 = blockIdx.x * BN;
    const int t = threadIdx.x;
    const int lda = TA ? Mdim : Kdim;
    const int ldb = TB ? Kdim : Ndim;
    const int w = t >> 5, lane = t & 31;
    const int wm0 = (w >> 1) * 32;   // 4 warp-rows of 32
    const int wn0 = (w & 1) * 64;    // 2 warp-cols of 64

    using AMaj = typename std::conditional<TA == 0, wmma::row_major, wmma::col_major>::type;
    using BMaj = typename std::conditional<TB == 0, wmma::row_major, wmma::col_major>::type;

    wmma::fragment<wmma::accumulator, 16, 16, 16, float> cf[2][4];
#pragma unroll
    for (int i = 0; i < 2; i++)
#pragma unroll
        for (int j = 0; j < 4; j++) wmma::fill_fragment(cf[i][j], 0.0f);

    float rs = 0.f;   // per-thread running row sum (EPI==16, thread t owns row t)

    auto issue = [&](int k0, int stg) {
        __half* As = smem + stg * STAGE;
        __half* Bs = As + A_HALVES;
#pragma unroll
        for (int i = 0; i < 2; i++) {
            int c = t + i * 256;
            if constexpr (TA == 0) {
                int m = c >> 2, kc = (c & 3) << 3;
                cp_async16(As + m * LD_K + kc,
                           A + (long long)(row0 + m) * lda + k0 + kc);
            } else {
                int k = c >> 4, mc = (c & 15) << 3;
                cp_async16(As + k * LD_MN + mc,
                           A + (long long)(k0 + k) * lda + row0 + mc);
            }
        }
#pragma unroll
        for (int i = 0; i < 2; i++) {
            int c = t + i * 256;
            if constexpr (TB == 0) {
                int k = c >> 4, nc = (c & 15) << 3;
                cp_async16(Bs + k * LD_MN + nc,
                           B + (long long)(k0 + k) * ldb + col0 + nc);
            } else {
                int n = c >> 2, kc = (c & 3) << 3;
                cp_async16(Bs + n * LD_K + kc,
                           B + (long long)(col0 + n) * ldb + k0 + kc);
            }
        }
        cp_commit();
    };

    const int T = Kdim / BK;
    issue(0, 0);
    for (int it = 0; it < T; it++) {
        cp_wait_all();
        __syncthreads();
        if (it + 1 < T) issue((it + 1) * BK, (it + 1) & 1);

        const __half* As = smem + (it & 1) * STAGE;
        const __half* Bs = As + A_HALVES;

        if constexpr (EPI == 16) {   // TA==0: As[m][k], row sums for softmax denom
            if (t < BM) {
                const __half* r = As + t * LD_K;
                float s = 0.f;
#pragma unroll
                for (int kk = 0; kk < BK; kk += 2) {
                    float2 f2 = __half22float2(*(const __half2*)(r + kk));
                    s += f2.x + f2.y;
                }
                rs += s;
            }
        }

#pragma unroll
        for (int ks = 0; ks < BK; ks += 16) {
            wmma::fragment<wmma::matrix_b, 16, 16, 16, __half, BMaj> bf[4];
#pragma unroll
            for (int j = 0; j < 4; j++) {
                const __half* pB = TB ? Bs + (wn0 + j * 16) * LD_K + ks
                                      : Bs + ks * LD_MN + wn0 + j * 16;
                wmma::load_matrix_sync(bf[j], pB, TB ? LD_K : LD_MN);
            }
#pragma unroll
            for (int mi = 0; mi < 2; mi++) {
                wmma::fragment<wmma::matrix_a, 16, 16, 16, __half, AMaj> af;
                const __half* pA = TA ? As + ks * LD_MN + wm0 + mi * 16
                                      : As + (wm0 + mi * 16) * LD_K + ks;
                wmma::load_matrix_sync(af, pA, TA ? LD_MN : LD_K);
#pragma unroll
                for (int j = 0; j < 4; j++)
                    wmma::mma_sync(cf[mi][j], af, bf[j], cf[mi][j]);
            }
        }
        __syncthreads();
    }

    if constexpr (EPI == 16) {
        if (t < BM) rowsumS[t] = 1.f / rs;
        __syncthreads();
    }

    // ---------- epilogue via per-warp smem buffer ----------
    float* ep = Es + w * 16 * 68;
#pragma unroll
    for (int mi = 0; mi < 2; mi++) {
#pragma unroll
        for (int j = 0; j < 4; j++)
            wmma::store_matrix_sync(ep + j * 16, cf[mi][j], 68, wmma::mem_row_major);
        __syncwarp();
#pragma unroll
        for (int it = 0; it < 8; it++) {
            int idx = it * 32 + lane;
            int r = idx >> 4, c4 = (idx & 15) << 2;
            float4 v = *(float4*)(ep + r * 68 + c4);
            int gr = row0 + wm0 + mi * 16 + r;
            int gc = col0 + wn0 + c4;
            if constexpr (EPI == 1) {
                float bb = biasRow[gr];
                v.x += bb; v.y += bb; v.z += bb; v.w += bb;
            }
            if constexpr (EPI == 2) {
                v.x *= alpha; v.y *= alpha; v.z *= alpha; v.w *= alpha;
            }
            if constexpr (EPI == 4) {
                v.x = fmaxf(fmaf(v.x, scaleCol[gc + 0], addCol[gc + 0]), 0.f);
                v.y = fmaxf(fmaf(v.y, scaleCol[gc + 1], addCol[gc + 1]), 0.f);
                v.z = fmaxf(fmaf(v.z, scaleCol[gc + 2], addCol[gc + 2]), 0.f);
                v.w = fmaxf(fmaf(v.w, scaleCol[gc + 3], addCol[gc + 3]), 0.f);
            }
            if constexpr (EPI == 8) {   // p = exp(scale * e), no max-subtract (|e|<~2)
                v.x = __expf(v.x * alpha); v.y = __expf(v.y * alpha);
                v.z = __expf(v.z * alpha); v.w = __expf(v.w * alpha);
            }
            if constexpr (EPI == 16) {  // normalize by row sum of p
                float inv = rowsumS[wm0 + mi * 16 + r];
                v.x *= inv; v.y *= inv; v.z *= inv; v.w *= inv;
            }
            if constexpr (sizeof(CT) == 2) {
                __half h[4] = { __float2half_rn(v.x), __float2half_rn(v.y),
                                __float2half_rn(v.z), __float2half_rn(v.w) };
                *(uint2*)((__half*)C + (long long)gr * Ndim + gc) = *(uint2*)h;
            } else {
                *(float4*)((float*)C + (long long)gr * Ndim + gc) = v;
            }
        }
        __syncwarp();
    }
}

// ---------------- launch ----------------
extern "C" void kernel_launch(void* const* d_in, const int* in_sizes, int n_in,
                              void* d_out, int out_size) {
    const float* x     = (const float*)d_in[0];
    const float* y     = (const float*)d_in[1];
    const float* w_qk  = (const float*)d_in[2];
    const float* w_v   = (const float*)d_in[3];
    const float* b_v   = (const float*)d_in[4];
    const float* w_t   = (const float*)d_in[5];
    const float* b_t   = (const float*)d_in[6];
    const float* gamma = (const float*)d_in[7];
    const float* beta  = (const float*)d_in[8];
    const float* rmean = (const float*)d_in[9];
    const float* rvar  = (const float*)d_in[10];
    float* out = (float*)d_out;

    __half *xh, *yh, *wqk, *wv, *wt, *q, *k, *v, *p, *o;
    float *inv, *cadd;
    cudaGetSymbolAddress((void**)&xh,   g_xh);
    cudaGetSymbolAddress((void**)&yh,   g_yh);
    cudaGetSymbolAddress((void**)&wqk,  g_wqk);
    cudaGetSymbolAddress((void**)&wv,   g_wv);
    cudaGetSymbolAddress((void**)&wt,   g_wt);
    cudaGetSymbolAddress((void**)&q,    g_q);
    cudaGetSymbolAddress((void**)&k,    g_kx);
    cudaGetSymbolAddress((void**)&v,    g_v);
    cudaGetSymbolAddress((void**)&p,    g_p);
    cudaGetSymbolAddress((void**)&o,    g_o);
    cudaGetSymbolAddress((void**)&inv,  g_inv);
    cudaGetSymbolAddress((void**)&cadd, g_cadd);

    const float scale = 0.088388347648318447f;  // 1/sqrt(128)

    {
        int n4 = BSZ * CDIM * NN / 4;
        f2h_k<<<(n4 + 255) / 256, 256>>>(x, xh, n4);
        f2h_k<<<(n4 + 255) / 256, 256>>>(y, yh, n4);
        int w4a = DAD * CDIM / 4;
        f2h_k<<<(w4a + 255) / 256, 256>>>(w_qk, wqk, w4a);
        int w4b = CDIM * CDIM / 4;
        f2h_k<<<(w4b + 255) / 256, 256>>>(w_v, wv, w4b);
        f2h_k<<<(w4b + 255) / 256, 256>>>(w_t, wt, w4b);
    }
    precomp_k<<<1, 512>>>(gamma, beta, rmean, rvar, b_t);

    // q = w_qk @ x -> half
    hgemm_k<0, 0, 0, __half><<<dim3(NN / BN, DAD / BM, BSZ), 256>>>(
        wqk, xh, q, DAD, NN, CDIM, 0, (long long)CDIM * NN, (long long)DAD * NN,
        1.f, nullptr, nullptr, nullptr);

    // k = w_qk @ y -> half
    hgemm_k<0, 0, 0, __half><<<dim3(MM / BN, DAD / BM, BSZ), 256>>>(
        wqk, yh, k, DAD, MM, CDIM, 0, (long long)CDIM * MM, (long long)DAD * MM,
        1.f, nullptr, nullptr, nullptr);

    // v = w_v @ y + b_v -> half
    hgemm_k<0, 0, 1, __half><<<dim3(MM / BN, CDIM / BM, BSZ), 256>>>(
        wv, yh, v, CDIM, MM, CDIM, 0, (long long)CDIM * MM, (long long)CDIM * MM,
        1.f, b_v, nullptr, nullptr);

    // p[n,m] = exp(scale * sum_d q[d,n]k[d,m]) -> half (unnormalized softmax num.)
    hgemm_k<1, 0, 8, __half><<<dim3(MM / BN, NN / BM, BSZ), 256>>>(
        q, k, p, NN, MM, DAD, (long long)DAD * NN, (long long)DAD * MM,
        (long long)NN * MM, scale, nullptr, nullptr, nullptr);

    // o[n,c] = (sum_m p[n,m] v[c,m]) / (sum_m p[n,m]) : row sums computed in-loop
    hgemm_k<0, 1, 16, __half><<<dim3(CDIM / BN, NN / BM, BSZ), 256>>>(
        p, v, o, NN, CDIM, MM, (long long)NN * MM, (long long)CDIM * MM,
        (long long)NN * CDIM, 1.f, nullptr, nullptr, nullptr);

    // out[bn,co] = relu((sum_c o[bn,c] w_t[co,c]) * inv[co] + cadd[co]) -> fp32
    hgemm_k<0, 1, 4, float><<<dim3(CDIM / BN, (BSZ * NN) / BM, 1), 256>>>(
        o, wt, out, BSZ * NN, CDIM, CDIM, 0, 0, 0,
        1.f, nullptr, inv, cadd);
}

// round 7
// speedup vs baseline: 1.6941x; 1.6941x over previous
#include <cuda_runtime.h>
#include <cuda_fp16.h>
#include <mma.h>
#include <math.h>
#include <cstdint>
#include <type_traits>
using namespace nvcuda;

#define BSZ 4
#define CDIM 512
#define NN 4096
#define MM 4096
#define DAD 128

#define BM 128
#define BN 128
#define BK 32
// padded smem leading dims (halves)
#define LD_K  40    // rows of BK(+8)   : [*][k]
#define LD_MN 136   // rows of 128(+8)  : [*][m or n]

// ---------------- scratch (device globals; no allocation) ----------------
__device__ __half g_xh[BSZ * CDIM * NN];
__device__ __half g_yh[BSZ * CDIM * MM];
__device__ __half g_wqk[DAD * CDIM];
__device__ __half g_wv[CDIM * CDIM];
__device__ __half g_wt[CDIM * CDIM];
__device__ __half g_q[BSZ * DAD * NN];           // [B,128,4096]
__device__ __half g_kx[BSZ * DAD * MM];          // [B,128,4096]
__device__ __half g_v[BSZ * CDIM * MM];          // [B,512,4096]
__device__ __half g_p[(size_t)BSZ * NN * MM];    // unnormalized exp(energy), half
__device__ __half g_o[BSZ * NN * CDIM];          // [B,4096,512]
__device__ float  g_inv[CDIM];
__device__ float  g_cadd[CDIM];

// ---------------- helpers ----------------
__device__ __forceinline__ void cp_async16(void* smem, const void* gmem) {
    unsigned s = (unsigned)__cvta_generic_to_shared(smem);
    asm volatile("cp.async.cg.shared.global [%0], [%1], 16;\n" :: "r"(s), "l"(gmem));
}
__device__ __forceinline__ void cp_commit() {
    asm volatile("cp.async.commit_group;\n");
}
__device__ __forceinline__ void cp_wait_all() {
    asm volatile("cp.async.wait_group 0;\n");
}

// ---------------- fp32 -> fp16 convert ----------------
__global__ void f2h_k(const float* __restrict__ in, __half* __restrict__ out, int n4) {
    int i = blockIdx.x * blockDim.x + threadIdx.x;
    if (i < n4) {
        float4 v = ((const float4*)in)[i];
        __half h[4] = { __float2half_rn(v.x), __float2half_rn(v.y),
                        __float2half_rn(v.z), __float2half_rn(v.w) };
        ((uint2*)out)[i] = *(uint2*)h;
    }
}

// ---------------- BN-fold precompute ----------------
__global__ void precomp_k(const float* __restrict__ gamma,
                          const float* __restrict__ beta,
                          const float* __restrict__ rmean,
                          const float* __restrict__ rvar,
                          const float* __restrict__ b_t) {
    int c = threadIdx.x;
    if (c < CDIM) {
        float inv = gamma[c] * rsqrtf(rvar[c] + 1e-5f);
        g_inv[c]  = inv;
        g_cadd[c] = b_t[c] * inv + beta[c] - rmean[c] * inv;
    }
}

// ---------------- pipelined tensor-core GEMM (half in, fp32 accum) ----------------
// C[m,n] = epi( sum_k A[m,k]*B[k,n] )
// TA=1: A stored [K,M] (lda=Mdim) -> smem As[k][m], col_major frag
// TA=0: A stored [M,K] (lda=Kdim) -> smem As[m][k], row_major frag
// TB=1: B stored [N,K] (ldb=Kdim) -> smem Bs[n][k], col_major frag
// TB=0: B stored [K,N] (ldb=Ndim) -> smem Bs[k][n], row_major frag
// EPI: 0 plain ; 1 +biasRow[m] ; 2 *alpha ; 4 relu(v*scaleCol[n]+addCol[n])
//      8 exp(alpha*v) ; 16 divide-by-rowsum-of-A (requires TA=0; softmax-normalize)
template <int TA, int TB, int EPI, typename CT>
__global__ __launch_bounds__(256)
void hgemm_k(const __half* __restrict__ Ag, const __half* __restrict__ Bg,
             CT* __restrict__ Cg,
             int Mdim, int Ndim, int Kdim,
             long long sA, long long sB, long long sC,
             float alpha,
             const float* __restrict__ biasRow,
             const float* __restrict__ scaleCol,
             const float* __restrict__ addCol) {
    constexpr int A_HALVES = TA ? BK * LD_MN : BM * LD_K;   // per stage
    constexpr int B_HALVES = TB ? BN * LD_K  : BK * LD_MN;
    constexpr int STAGE = A_HALVES + B_HALVES;
    __shared__ __align__(16) __half smem[2 * STAGE];
    __shared__ float rowsumS[BM];
    float* Es = (float*)smem;   // epilogue reuse

    const __half* A = Ag + (long long)blockIdx.z * sA;
    const __half* B = Bg + (long long)blockIdx.z * sB;
    CT*           C = Cg + (long long)blockIdx.z * sC;

    const int row0 = blockIdx.y * BM;
    const int col0 = blockIdx.x * BN;
    const int t = threadIdx.x;
    const int lda = TA ? Mdim : Kdim;
    const int ldb = TB ? Kdim : Ndim;
    const int w = t >> 5, lane = t & 31;
    const int wm0 = (w >> 1) * 32;   // 4 warp-rows of 32
    const int wn0 = (w & 1) * 64;    // 2 warp-cols of 64

    using AMaj = typename std::conditional<TA == 0, wmma::row_major, wmma::col_major>::type;
    using BMaj = typename std::conditional<TB == 0, wmma::row_major, wmma::col_major>::type;

    wmma::fragment<wmma::accumulator, 16, 16, 16, float> cf[2][4];
#pragma unroll
    for (int i = 0; i < 2; i++)
#pragma unroll
        for (int j = 0; j < 4; j++) wmma::fill_fragment(cf[i][j], 0.0f);

    float rs = 0.f;   // per-thread running row sum (EPI==16, thread t owns row t)

    auto issue = [&](int k0, int stg) {
        __half* As = smem + stg * STAGE;
        __half* Bs = As + A_HALVES;
#pragma unroll
        for (int i = 0; i < 2; i++) {
            int c = t + i * 256;
            if constexpr (TA == 0) {
                int m = c >> 2, kc = (c & 3) << 3;
                cp_async16(As + m * LD_K + kc,
                           A + (long long)(row0 + m) * lda + k0 + kc);
            } else {
                int k = c >> 4, mc = (c & 15) << 3;
                cp_async16(As + k * LD_MN + mc,
                           A + (long long)(k0 + k) * lda + row0 + mc);
            }
        }
#pragma unroll
        for (int i = 0; i < 2; i++) {
            int c = t + i * 256;
            if constexpr (TB == 0) {
                int k = c >> 4, nc = (c & 15) << 3;
                cp_async16(Bs + k * LD_MN + nc,
                           B + (long long)(k0 + k) * ldb + col0 + nc);
            } else {
                int n = c >> 2, kc = (c & 3) << 3;
                cp_async16(Bs + n * LD_K + kc,
                           B + (long long)(col0 + n) * ldb + k0 + kc);
            }
        }
        cp_commit();
    };

    const int T = Kdim / BK;
    issue(0, 0);
    for (int it = 0; it < T; it++) {
        cp_wait_all();
        __syncthreads();
        if (it + 1 < T) issue((it + 1) * BK, (it + 1) & 1);

        const __half* As = smem + (it & 1) * STAGE;
        const __half* Bs = As + A_HALVES;

        if constexpr (EPI == 16) {   // TA==0: As[m][k], row sums for softmax denom
            if (t < BM) {
                const __half* r = As + t * LD_K;
                float s = 0.f;
#pragma unroll
                for (int kk = 0; kk < BK; kk += 2) {
                    float2 f2 = __half22float2(*(const __half2*)(r + kk));
                    s += f2.x + f2.y;
                }
                rs += s;
            }
        }

#pragma unroll
        for (int ks = 0; ks < BK; ks += 16) {
            wmma::fragment<wmma::matrix_b, 16, 16, 16, __half, BMaj> bf[4];
#pragma unroll
            for (int j = 0; j < 4; j++) {
                const __half* pB = TB ? Bs + (wn0 + j * 16) * LD_K + ks
                                      : Bs + ks * LD_MN + wn0 + j * 16;
                wmma::load_matrix_sync(bf[j], pB, TB ? LD_K : LD_MN);
            }
#pragma unroll
            for (int mi = 0; mi < 2; mi++) {
                wmma::fragment<wmma::matrix_a, 16, 16, 16, __half, AMaj> af;
                const __half* pA = TA ? As + ks * LD_MN + wm0 + mi * 16
                                      : As + (wm0 + mi * 16) * LD_K + ks;
                wmma::load_matrix_sync(af, pA, TA ? LD_MN : LD_K);
#pragma unroll
                for (int j = 0; j < 4; j++)
                    wmma::mma_sync(cf[mi][j], af, bf[j], cf[mi][j]);
            }
        }
        __syncthreads();
    }

    if constexpr (EPI == 16) {
        if (t < BM) rowsumS[t] = 1.f / rs;
        __syncthreads();
    }

    // ---------- epilogue via per-warp smem buffer ----------
    float* ep = Es + w * 16 * 68;
#pragma unroll
    for (int mi = 0; mi < 2; mi++) {
#pragma unroll
        for (int j = 0; j < 4; j++)
            wmma::store_matrix_sync(ep + j * 16, cf[mi][j], 68, wmma::mem_row_major);
        __syncwarp();
#pragma unroll
        for (int it = 0; it < 8; it++) {
            int idx = it * 32 + lane;
            int r = idx >> 4, c4 = (idx & 15) << 2;
            float4 v = *(float4*)(ep + r * 68 + c4);
            int gr = row0 + wm0 + mi * 16 + r;
            int gc = col0 + wn0 + c4;
            if constexpr (EPI == 1) {
                float bb = biasRow[gr];
                v.x += bb; v.y += bb; v.z += bb; v.w += bb;
            }
            if constexpr (EPI == 2) {
                v.x *= alpha; v.y *= alpha; v.z *= alpha; v.w *= alpha;
            }
            if constexpr (EPI == 4) {
                v.x = fmaxf(fmaf(v.x, scaleCol[gc + 0], addCol[gc + 0]), 0.f);
                v.y = fmaxf(fmaf(v.y, scaleCol[gc + 1], addCol[gc + 1]), 0.f);
                v.z = fmaxf(fmaf(v.z, scaleCol[gc + 2], addCol[gc + 2]), 0.f);
                v.w = fmaxf(fmaf(v.w, scaleCol[gc + 3], addCol[gc + 3]), 0.f);
            }
            if constexpr (EPI == 8) {   // p = exp(scale * e), no max-subtract (|e|<~2)
                v.x = __expf(v.x * alpha); v.y = __expf(v.y * alpha);
                v.z = __expf(v.z * alpha); v.w = __expf(v.w * alpha);
            }
            if constexpr (EPI == 16) {  // normalize by row sum of p
                float inv = rowsumS[wm0 + mi * 16 + r];
                v.x *= inv; v.y *= inv; v.z *= inv; v.w *= inv;
            }
            if constexpr (sizeof(CT) == 2) {
                __half h[4] = { __float2half_rn(v.x), __float2half_rn(v.y),
                                __float2half_rn(v.z), __float2half_rn(v.w) };
                *(uint2*)((__half*)C + (long long)gr * Ndim + gc) = *(uint2*)h;
            } else {
                *(float4*)((float*)C + (long long)gr * Ndim + gc) = v;
            }
        }
        __syncwarp();
    }
}

// ---------------- launch ----------------
extern "C" void kernel_launch(void* const* d_in, const int* in_sizes, int n_in,
                              void* d_out, int out_size) {
    const float* x     = (const float*)d_in[0];
    const float* y     = (const float*)d_in[1];
    const float* w_qk  = (const float*)d_in[2];
    const float* w_v   = (const float*)d_in[3];
    const float* b_v   = (const float*)d_in[4];
    const float* w_t   = (const float*)d_in[5];
    const float* b_t   = (const float*)d_in[6];
    const float* gamma = (const float*)d_in[7];
    const float* beta  = (const float*)d_in[8];
    const float* rmean = (const float*)d_in[9];
    const float* rvar  = (const float*)d_in[10];
    float* out = (float*)d_out;

    __half *xh, *yh, *wqk, *wv, *wt, *q, *k, *v, *p, *o;
    float *inv, *cadd;
    cudaGetSymbolAddress((void**)&xh,   g_xh);
    cudaGetSymbolAddress((void**)&yh,   g_yh);
    cudaGetSymbolAddress((void**)&wqk,  g_wqk);
    cudaGetSymbolAddress((void**)&wv,   g_wv);
    cudaGetSymbolAddress((void**)&wt,   g_wt);
    cudaGetSymbolAddress((void**)&q,    g_q);
    cudaGetSymbolAddress((void**)&k,    g_kx);
    cudaGetSymbolAddress((void**)&v,    g_v);
    cudaGetSymbolAddress((void**)&p,    g_p);
    cudaGetSymbolAddress((void**)&o,    g_o);
    cudaGetSymbolAddress((void**)&inv,  g_inv);
    cudaGetSymbolAddress((void**)&cadd, g_cadd);

    const float scale = 0.088388347648318447f;  // 1/sqrt(128)

    {
        int n4 = BSZ * CDIM * NN / 4;
        f2h_k<<<(n4 + 255) / 256, 256>>>(x, xh, n4);
        f2h_k<<<(n4 + 255) / 256, 256>>>(y, yh, n4);
        int w4a = DAD * CDIM / 4;
        f2h_k<<<(w4a + 255) / 256, 256>>>(w_qk, wqk, w4a);
        int w4b = CDIM * CDIM / 4;
        f2h_k<<<(w4b + 255) / 256, 256>>>(w_v, wv, w4b);
        f2h_k<<<(w4b + 255) / 256, 256>>>(w_t, wt, w4b);
    }
    precomp_k<<<1, 512>>>(gamma, beta, rmean, rvar, b_t);

    // q = w_qk @ x -> half
    hgemm_k<0, 0, 0, __half><<<dim3(NN / BN, DAD / BM, BSZ), 256>>>(
        wqk, xh, q, DAD, NN, CDIM, 0, (long long)CDIM * NN, (long long)DAD * NN,
        1.f, nullptr, nullptr, nullptr);

    // k = w_qk @ y -> half
    hgemm_k<0, 0, 0, __half><<<dim3(MM / BN, DAD / BM, BSZ), 256>>>(
        wqk, yh, k, DAD, MM, CDIM, 0, (long long)CDIM * MM, (long long)DAD * MM,
        1.f, nullptr, nullptr, nullptr);

    // v = w_v @ y + b_v -> half
    hgemm_k<0, 0, 1, __half><<<dim3(MM / BN, CDIM / BM, BSZ), 256>>>(
        wv, yh, v, CDIM, MM, CDIM, 0, (long long)CDIM * MM, (long long)CDIM * MM,
        1.f, b_v, nullptr, nullptr);

    // p[n,m] = exp(scale * sum_d q[d,n]k[d,m]) -> half (unnormalized softmax num.)
    hgemm_k<1, 0, 8, __half><<<dim3(MM / BN, NN / BM, BSZ), 256>>>(
        q, k, p, NN, MM, DAD, (long long)DAD * NN, (long long)DAD * MM,
        (long long)NN * MM, scale, nullptr, nullptr, nullptr);

    // o[n,c] = (sum_m p[n,m] v[c,m]) / (sum_m p[n,m]) : row sums computed in-loop
    hgemm_k<0, 1, 16, __half><<<dim3(CDIM / BN, NN / BM, BSZ), 256>>>(
        p, v, o, NN, CDIM, MM, (long long)NN * MM, (long long)CDIM * MM,
        (long long)NN * CDIM, 1.f, nullptr, nullptr, nullptr);

    // out[bn,co] = relu((sum_c o[bn,c] w_t[co,c]) * inv[co] + cadd[co]) -> fp32
    hgemm_k<0, 1, 4, float><<<dim3(CDIM / BN, (BSZ * NN) / BM, 1), 256>>>(
        o, wt, out, BSZ * NN, CDIM, CDIM, 0, 0, 0,
        1.f, nullptr, inv, cadd);
}